// round 4
// baseline (speedup 1.0000x reference)
#include <cuda_runtime.h>

// SSIM over 11x11 patches — 4 outputs (views) per warp, register-trimmed.
// img_pred: [4, 2048, 16, 121, 3] f32   (~190 MB)
// img_gt:   [2048, 16, 121, 3] f32      (~47.6 MB)
// out:      [4, 2048, 16] f32
//
// R3 -> R4: dedupe gt accumulators (the bit-16 fold produces the full
// cross-half sum from a single copy; duplication was wasted registers and
// flops) and force 4 blocks/SM via __launch_bounds__(256, 4) to lift
// occupancy from 24 to 32 warps/SM. Everything else as R3: coalesced
// element-linear streaming, channel-congruence slots with one per-lane
// rotate, fold across lane-bit-16 then 4-level butterfly per 16-lane half.

#define NN      2048
#define NP      16
#define ROW     363                      // 121 patches * 3 channels
#define VSTRIDE ((size_t)NN * NP * ROW)  // floats per view

__global__ __launch_bounds__(256, 4) void ssim_kernel(
    const float* __restrict__ pred,
    const float* __restrict__ gt,
    float* __restrict__ out)
{
    __shared__ float we[384];   // expanded per-element weights, zero-padded

    const int tid = threadIdx.x;

    // Build expanded normalized gaussian window: we[e] = win[e/3], 0 for e>=363.
    {
        const float inv2s2 = 1.0f / 4.5f;   // 1/(2*sigma^2), sigma=1.5
        float S = 0.0f;
        #pragma unroll
        for (int i = 0; i < 11; i++) {
            float d = (float)(i - 5);
            S += expf(-d * d * inv2s2);
        }
        const float invS2 = 1.0f / (S * S);
        for (int e = tid; e < 384; e += 256) {
            int patch = e / 3;
            int py = patch / 11, px = patch % 11;
            float dy = (float)(py - 5), dx = (float)(px - 5);
            float v = expf(-(dx * dx + dy * dy) * inv2s2) * invS2;
            we[e] = (e < ROW) ? v : 0.0f;
        }
    }
    __syncthreads();

    const int warp = blockIdx.x * (blockDim.x >> 5) + (tid >> 5);
    const int lane = tid & 31;

    const int n = warp >> 4;       // 0..2047
    const int p = warp & 15;       // 0..15

    const size_t rowoff = (size_t)(n * NP + p) * ROW;
    const float* __restrict__ g0 = gt + rowoff;
    const float* __restrict__ p0 = pred + rowoff;
    const float* __restrict__ p1 = p0 + VSTRIDE;
    const float* __restrict__ p2v = p0 + 2 * VSTRIDE;
    const float* __restrict__ p3 = p0 + 3 * VSTRIDE;

    // Congruence-slot accumulators. Slot j holds channel (j + lane%3) % 3.
    // Per view: m1 (sum w*a), q2 (sum w*a*a), pg (sum w*a*b).
    // gt stats: SINGLE copy (fold replicates the total into both halves).
    float m1[4][3], q2[4][3], pg[4][3];
    float m2[3], g2[3];
    #pragma unroll
    for (int v = 0; v < 4; v++)
        #pragma unroll
        for (int j = 0; j < 3; j++) { m1[v][j] = 0.f; q2[v][j] = 0.f; pg[v][j] = 0.f; }
    #pragma unroll
    for (int j = 0; j < 3; j++) { m2[j] = 0.f; g2[j] = 0.f; }

    // Main: k = 0..10 full warps of 32 elements (352 elems), tail below.
    #pragma unroll
    for (int k = 0; k < 11; k++) {
        const int e = k * 32 + lane;
        const int j = (2 * k) % 3;          // compile-time slot
        const float w = we[e];
        const float b = g0[e];
        const float wb = w * b;
        m2[j] += wb;
        g2[j] += wb * b;
        {   float a = p0[e]; float wa = w * a;
            m1[0][j] += wa; q2[0][j] += wa * a; pg[0][j] += wa * b; }
        {   float a = p1[e]; float wa = w * a;
            m1[1][j] += wa; q2[1][j] += wa * a; pg[1][j] += wa * b; }
        {   float a = p2v[e]; float wa = w * a;
            m1[2][j] += wa; q2[2][j] += wa * a; pg[2][j] += wa * b; }
        {   float a = p3[e]; float wa = w * a;
            m1[3][j] += wa; q2[3][j] += wa * a; pg[3][j] += wa * b; }
    }
    // Tail: k=11, elements 352..362 (11 valid lanes), slot j = 22%3 = 1.
    if (lane < 11) {
        const int e = 352 + lane;
        const int j = 1;
        const float w = we[e];
        const float b = g0[e];
        const float wb = w * b;
        m2[j] += wb;
        g2[j] += wb * b;
        {   float a = p0[e]; float wa = w * a;
            m1[0][j] += wa; q2[0][j] += wa * a; pg[0][j] += wa * b; }
        {   float a = p1[e]; float wa = w * a;
            m1[1][j] += wa; q2[1][j] += wa * a; pg[1][j] += wa * b; }
        {   float a = p2v[e]; float wa = w * a;
            m1[2][j] += wa; q2[2][j] += wa * a; pg[2][j] += wa * b; }
        {   float a = p3[e]; float wa = w * a;
            m1[3][j] += wa; q2[3][j] += wa * a; pg[3][j] += wa * b; }
    }

    // Rotate congruence slots into true channel order.
    // True channel c lives in slot (c - r + 3) % 3, r = lane % 3:
    //   r=0: (s0,s1,s2)  r=1: (s2,s0,s1)  r=2: (s1,s2,s0)
    const int r = lane - (lane / 3) * 3;
    const bool r1f = (r == 1);
    const bool r2f = (r == 2);
    #define ROT3(s) do { \
        float t0 = (s)[0], t1 = (s)[1], t2 = (s)[2]; \
        (s)[0] = r1f ? t2 : (r2f ? t1 : t0); \
        (s)[1] = r1f ? t0 : (r2f ? t2 : t1); \
        (s)[2] = r1f ? t1 : (r2f ? t0 : t2); \
    } while (0)
    #pragma unroll
    for (int v = 0; v < 4; v++) { ROT3(m1[v]); ROT3(q2[v]); ROT3(pg[v]); }
    ROT3(m2); ROT3(g2);
    #undef ROT3

    // Fold across lane-bit-16. After the fold:
    //  lanes 0-15  carry views 0,1 + full-gt stats
    //  lanes 16-31 carry views 2,3 + full-gt stats
    // layout: [0..2] m1_lo  [3..5] q2_lo  [6..8] pg_lo
    //         [9..11] m1_hi [12..14] q2_hi [15..17] pg_hi
    //         [18..20] m2   [21..23] g2
    const bool hi = (lane & 16) != 0;
    float val[24];
    #pragma unroll
    for (int j = 0; j < 3; j++) {
        float kA, kB;
        #define FOLD(slotA, slotB, idx) \
            kA = (slotA); kB = (slotB); \
            { float keep = hi ? kB : kA; float send = hi ? kA : kB; \
              val[idx] = keep + __shfl_xor_sync(0xFFFFFFFFu, send, 16); }
        FOLD(m1[0][j], m1[2][j], 0 + j);
        FOLD(q2[0][j], q2[2][j], 3 + j);
        FOLD(pg[0][j], pg[2][j], 6 + j);
        FOLD(m1[1][j], m1[3][j], 9 + j);
        FOLD(q2[1][j], q2[3][j], 12 + j);
        FOLD(pg[1][j], pg[3][j], 15 + j);
        FOLD(m2[j],    m2[j],    18 + j);   // single copy -> both halves get total
        FOLD(g2[j],    g2[j],    21 + j);
        #undef FOLD
    }

    // Butterfly within each 16-lane half.
    #pragma unroll
    for (int off = 8; off; off >>= 1) {
        #pragma unroll
        for (int i = 0; i < 24; i++)
            val[i] += __shfl_xor_sync(0xFFFFFFFFu, val[i], off);
    }

    // Epilogue: each lane computes SSIM for its half's two views.
    const float C1 = 1e-4f;   // 0.01^2
    const float C2 = 9e-4f;   // 0.03^2
    float ssim_lo = 0.f, ssim_hi_v = 0.f;
    #pragma unroll
    for (int c = 0; c < 3; c++) {
        float mu2  = val[18 + c];
        float mu2sq = mu2 * mu2;
        float s2   = val[21 + c] - mu2sq;
        {   // view lo
            float mu1 = val[0 + c];
            float mu1sq = mu1 * mu1;
            float mu12  = mu1 * mu2;
            float s1  = val[3 + c] - mu1sq;
            float s12 = val[6 + c] - mu12;
            float num = (2.0f * mu12 + C1) * (2.0f * s12 + C2);
            float den = (mu1sq + mu2sq + C1) * (s1 + s2 + C2);
            ssim_lo += __fdividef(num, den);
        }
        {   // view hi
            float mu1 = val[9 + c];
            float mu1sq = mu1 * mu1;
            float mu12  = mu1 * mu2;
            float s1  = val[12 + c] - mu1sq;
            float s12 = val[15 + c] - mu12;
            float num = (2.0f * mu12 + C1) * (2.0f * s12 + C2);
            float den = (mu1sq + mu2sq + C1) * (s1 + s2 + C2);
            ssim_hi_v += __fdividef(num, den);
        }
    }

    // Writers: lanes 0,1 (views 0,1) and 16,17 (views 2,3).
    if ((lane & 14) == 0) {
        int sel  = lane & 1;
        int view = ((lane >> 4) << 1) | sel;
        float res = (sel ? ssim_hi_v : ssim_lo) * (1.0f / 3.0f);
        out[(view * NN + n) * NP + p] = res;
    }
}

extern "C" void kernel_launch(void* const* d_in, const int* in_sizes, int n_in,
                              void* d_out, int out_size)
{
    const float* pred = (const float*)d_in[0];   // img_pred [4,2048,16,121,3]
    const float* gt   = (const float*)d_in[1];   // img_gt   [2048,16,121,3]
    float* out = (float*)d_out;                  // [4,2048,16]

    const int total_warps = NN * NP;             // 32768 warps, 4 outputs each
    const int warps_per_block = 8;
    const int blocks = total_warps / warps_per_block;  // 4096

    ssim_kernel<<<blocks, 256>>>(pred, gt, out);
}

// round 5
// speedup vs baseline: 1.6392x; 1.6392x over previous
#include <cuda_runtime.h>

// SSIM over 11x11 patches — 4 views per warp + explicit load pipeline.
// img_pred: [4, 2048, 16, 121, 3] f32   (~190 MB)
// img_gt:   [2048, 16, 121, 3] f32      (~47.6 MB)
// out:      [4, 2048, 16] f32
//
// R4 lesson: forcing low regs killed MLP (issue 45->28%, DRAM 50->32%).
// R5 = R3 structure (natural regs, 3 blocks/SM) + gt-accumulator dedupe
// (from R4, pure win) + explicit 2-stage software pipeline so ~10 LDGs are
// in flight per warp independent of ptxas scheduling. __ldcs on pred
// (pure stream, evict-first).

#define NN      2048
#define NP      16
#define ROW     363                      // 121 patches * 3 channels
#define VSTRIDE ((size_t)NN * NP * ROW)  // floats per view

__global__ __launch_bounds__(256) void ssim_kernel(
    const float* __restrict__ pred,
    const float* __restrict__ gt,
    float* __restrict__ out)
{
    __shared__ float we[384];   // expanded per-element weights, zero-padded

    const int tid = threadIdx.x;

    // Build expanded normalized gaussian window: we[e] = win[e/3], 0 for e>=363.
    {
        const float inv2s2 = 1.0f / 4.5f;   // 1/(2*sigma^2), sigma=1.5
        float S = 0.0f;
        #pragma unroll
        for (int i = 0; i < 11; i++) {
            float d = (float)(i - 5);
            S += expf(-d * d * inv2s2);
        }
        const float invS2 = 1.0f / (S * S);
        for (int e = tid; e < 384; e += 256) {
            int patch = e / 3;
            int py = patch / 11, px = patch % 11;
            float dy = (float)(py - 5), dx = (float)(px - 5);
            float v = expf(-(dx * dx + dy * dy) * inv2s2) * invS2;
            we[e] = (e < ROW) ? v : 0.0f;
        }
    }
    __syncthreads();

    const int warp = blockIdx.x * (blockDim.x >> 5) + (tid >> 5);
    const int lane = tid & 31;

    const int n = warp >> 4;       // 0..2047
    const int p = warp & 15;       // 0..15

    const size_t rowoff = (size_t)(n * NP + p) * ROW;
    const float* __restrict__ g0 = gt + rowoff;
    const float* __restrict__ p0 = pred + rowoff;
    const float* __restrict__ p1 = p0 + VSTRIDE;
    const float* __restrict__ p2v = p0 + 2 * VSTRIDE;
    const float* __restrict__ p3 = p0 + 3 * VSTRIDE;

    // Congruence-slot accumulators. Slot j holds channel (j + lane%3) % 3.
    float m1[4][3], q2[4][3], pg[4][3];
    float m2[3], g2[3];
    #pragma unroll
    for (int v = 0; v < 4; v++)
        #pragma unroll
        for (int j = 0; j < 3; j++) { m1[v][j] = 0.f; q2[v][j] = 0.f; pg[v][j] = 0.f; }
    #pragma unroll
    for (int j = 0; j < 3; j++) { m2[j] = 0.f; g2[j] = 0.f; }

    // ---- software-pipelined main loop: 363 = 11*32 + 11 ----
    float wC, bC, a0C, a1C, a2C, a3C;
    {
        const int e = lane;
        wC  = we[e];
        bC  = g0[e];
        a0C = __ldcs(p0 + e);
        a1C = __ldcs(p1 + e);
        a2C = __ldcs(p2v + e);
        a3C = __ldcs(p3 + e);
    }

    #pragma unroll
    for (int k = 0; k < 12; k++) {
        // Prefetch next stage (k+1) before consuming current.
        float wN = 0.f, bN = 0.f, a0N = 0.f, a1N = 0.f, a2N = 0.f, a3N = 0.f;
        if (k < 10) {
            const int e = (k + 1) * 32 + lane;
            wN  = we[e];
            bN  = g0[e];
            a0N = __ldcs(p0 + e);
            a1N = __ldcs(p1 + e);
            a2N = __ldcs(p2v + e);
            a3N = __ldcs(p3 + e);
        } else if (k == 10) {
            // tail stage: elements 352..362, lanes 0..10 only
            if (lane < 11) {
                const int e = 352 + lane;
                wN  = we[e];
                bN  = g0[e];
                a0N = __ldcs(p0 + e);
                a1N = __ldcs(p1 + e);
                a2N = __ldcs(p2v + e);
                a3N = __ldcs(p3 + e);
            }
        }

        // Consume current stage. Slot j = (2k)%3 (compile-time).
        const int j = (2 * k) % 3;
        {
            const float w = wC;
            const float b = bC;
            const float wb = w * b;
            m2[j] += wb;
            g2[j] += wb * b;
            { float a = a0C; float wa = w * a;
              m1[0][j] += wa; q2[0][j] += wa * a; pg[0][j] += wa * b; }
            { float a = a1C; float wa = w * a;
              m1[1][j] += wa; q2[1][j] += wa * a; pg[1][j] += wa * b; }
            { float a = a2C; float wa = w * a;
              m1[2][j] += wa; q2[2][j] += wa * a; pg[2][j] += wa * b; }
            { float a = a3C; float wa = w * a;
              m1[3][j] += wa; q2[3][j] += wa * a; pg[3][j] += wa * b; }
        }

        wC = wN; bC = bN; a0C = a0N; a1C = a1N; a2C = a2N; a3C = a3N;
    }
    // Note: k=11 consumes the tail values loaded at k=10 (w=0 for invalid
    // lanes so their contribution is exactly zero); slot (2*11)%3 = 1 matches
    // the channel congruence of elements 352..362.

    // Rotate congruence slots into true channel order.
    // True channel c lives in slot (c - r + 3) % 3, r = lane % 3:
    //   r=0: (s0,s1,s2)  r=1: (s2,s0,s1)  r=2: (s1,s2,s0)
    const int r = lane - (lane / 3) * 3;
    const bool r1f = (r == 1);
    const bool r2f = (r == 2);
    #define ROT3(s) do { \
        float t0 = (s)[0], t1 = (s)[1], t2 = (s)[2]; \
        (s)[0] = r1f ? t2 : (r2f ? t1 : t0); \
        (s)[1] = r1f ? t0 : (r2f ? t2 : t1); \
        (s)[2] = r1f ? t1 : (r2f ? t0 : t2); \
    } while (0)
    #pragma unroll
    for (int v = 0; v < 4; v++) { ROT3(m1[v]); ROT3(q2[v]); ROT3(pg[v]); }
    ROT3(m2); ROT3(g2);
    #undef ROT3

    // Fold across lane-bit-16. After the fold:
    //  lanes 0-15  carry views 0,1 + full-gt stats
    //  lanes 16-31 carry views 2,3 + full-gt stats
    const bool hi = (lane & 16) != 0;
    float val[24];
    #pragma unroll
    for (int j = 0; j < 3; j++) {
        float kA, kB;
        #define FOLD(slotA, slotB, idx) \
            kA = (slotA); kB = (slotB); \
            { float keep = hi ? kB : kA; float send = hi ? kA : kB; \
              val[idx] = keep + __shfl_xor_sync(0xFFFFFFFFu, send, 16); }
        FOLD(m1[0][j], m1[2][j], 0 + j);
        FOLD(q2[0][j], q2[2][j], 3 + j);
        FOLD(pg[0][j], pg[2][j], 6 + j);
        FOLD(m1[1][j], m1[3][j], 9 + j);
        FOLD(q2[1][j], q2[3][j], 12 + j);
        FOLD(pg[1][j], pg[3][j], 15 + j);
        FOLD(m2[j],    m2[j],    18 + j);   // single copy -> both halves get total
        FOLD(g2[j],    g2[j],    21 + j);
        #undef FOLD
    }

    // Butterfly within each 16-lane half.
    #pragma unroll
    for (int off = 8; off; off >>= 1) {
        #pragma unroll
        for (int i = 0; i < 24; i++)
            val[i] += __shfl_xor_sync(0xFFFFFFFFu, val[i], off);
    }

    // Epilogue: each lane computes SSIM for its half's two views.
    const float C1 = 1e-4f;   // 0.01^2
    const float C2 = 9e-4f;   // 0.03^2
    float ssim_lo = 0.f, ssim_hi_v = 0.f;
    #pragma unroll
    for (int c = 0; c < 3; c++) {
        float mu2  = val[18 + c];
        float mu2sq = mu2 * mu2;
        float s2   = val[21 + c] - mu2sq;
        {   // view lo
            float mu1 = val[0 + c];
            float mu1sq = mu1 * mu1;
            float mu12  = mu1 * mu2;
            float s1  = val[3 + c] - mu1sq;
            float s12 = val[6 + c] - mu12;
            float num = (2.0f * mu12 + C1) * (2.0f * s12 + C2);
            float den = (mu1sq + mu2sq + C1) * (s1 + s2 + C2);
            ssim_lo += __fdividef(num, den);
        }
        {   // view hi
            float mu1 = val[9 + c];
            float mu1sq = mu1 * mu1;
            float mu12  = mu1 * mu2;
            float s1  = val[12 + c] - mu1sq;
            float s12 = val[15 + c] - mu12;
            float num = (2.0f * mu12 + C1) * (2.0f * s12 + C2);
            float den = (mu1sq + mu2sq + C1) * (s1 + s2 + C2);
            ssim_hi_v += __fdividef(num, den);
        }
    }

    // Writers: lanes 0,1 (views 0,1) and 16,17 (views 2,3).
    if ((lane & 14) == 0) {
        int sel  = lane & 1;
        int view = ((lane >> 4) << 1) | sel;
        float res = (sel ? ssim_hi_v : ssim_lo) * (1.0f / 3.0f);
        out[(view * NN + n) * NP + p] = res;
    }
}

extern "C" void kernel_launch(void* const* d_in, const int* in_sizes, int n_in,
                              void* d_out, int out_size)
{
    const float* pred = (const float*)d_in[0];   // img_pred [4,2048,16,121,3]
    const float* gt   = (const float*)d_in[1];   // img_gt   [2048,16,121,3]
    float* out = (float*)d_out;                  // [4,2048,16]

    const int total_warps = NN * NP;             // 32768 warps, 4 outputs each
    const int warps_per_block = 8;
    const int blocks = total_warps / warps_per_block;  // 4096

    ssim_kernel<<<blocks, 256>>>(pred, gt, out);
}

// round 6
// speedup vs baseline: 1.9532x; 1.1916x over previous
#include <cuda_runtime.h>
#include <cstdint>

// SSIM over 11x11 patches — cp.async block staging + smem compute.
// img_pred: [4, 2048, 16, 121, 3] f32   (~190 MB)
// img_gt:   [2048, 16, 121, 3] f32      (~47.6 MB)
// out:      [4, 2048, 16] f32
//
// Block (128 thr) = 4 consecutive (n,p) rows. 4 rows x 363 floats = 1452
// floats = 363 float4, 16B-aligned for every stream (gt + 4 pred views).
// Stage all 5 chunks into smem via cp.async.cg 16B (no register round-trip,
// deep MLP), sync, then warp w reduces row w for all 4 views from smem
// using the R5 congruence-slot / bit-16-fold / half-butterfly reduction.
// ~30.5 KB static smem -> ~6-7 blocks/SM; staging blocks saturate DRAM
// while sibling blocks compute.

#define NN       2048
#define NP       16
#define ROW      363                       // 121 patches * 3 channels
#define VSTRIDE  ((size_t)NN * NP * ROW)   // floats per view
#define RPB      4                         // rows per block
#define CHUNK    (RPB * ROW)               // 1452 floats
#define CHUNK4   (CHUNK / 4)               // 363 float4

__device__ __forceinline__ void cp16(uint32_t dst, const void* src) {
    asm volatile("cp.async.cg.shared.global [%0], [%1], 16;" :: "r"(dst), "l"(src));
}

__global__ __launch_bounds__(128) void ssim_kernel(
    const float* __restrict__ pred,
    const float* __restrict__ gt,
    float* __restrict__ out)
{
    __shared__ float sG[CHUNK];        // gt, 4 rows
    __shared__ float sP[4][CHUNK];     // pred, 4 views x 4 rows
    __shared__ float we[384];          // expanded per-element weights

    const int tid = threadIdx.x;

    // Build expanded normalized gaussian window: we[e] = win[e/3], 0 for e>=363.
    {
        const float inv2s2 = 1.0f / 4.5f;   // 1/(2*sigma^2), sigma=1.5
        float S = 0.0f;
        #pragma unroll
        for (int i = 0; i < 11; i++) {
            float d = (float)(i - 5);
            S += expf(-d * d * inv2s2);
        }
        const float invS2 = 1.0f / (S * S);
        for (int e = tid; e < 384; e += 128) {
            int patch = e / 3;
            int py = patch / 11, px = patch % 11;
            float dy = (float)(py - 5), dx = (float)(px - 5);
            float v = expf(-(dx * dx + dy * dy) * inv2s2) * invS2;
            we[e] = (e < ROW) ? v : 0.0f;
        }
    }

    // ---- stage: 5 streams x 363 float4 via cp.async ----
    const int q0 = blockIdx.x * RPB;                 // first row of this block
    {
        const uint32_t dG = (uint32_t)__cvta_generic_to_shared(sG);
        const float4* __restrict__ srcG =
            (const float4*)(gt + (size_t)q0 * ROW);
        for (int i = tid; i < CHUNK4; i += 128)
            cp16(dG + i * 16, srcG + i);

        #pragma unroll
        for (int v = 0; v < 4; v++) {
            const uint32_t dP = (uint32_t)__cvta_generic_to_shared(sP[v]);
            const float4* __restrict__ srcP =
                (const float4*)(pred + v * VSTRIDE + (size_t)q0 * ROW);
            for (int i = tid; i < CHUNK4; i += 128)
                cp16(dP + i * 16, srcP + i);
        }
    }
    asm volatile("cp.async.commit_group;");
    asm volatile("cp.async.wait_group 0;");
    __syncthreads();   // also covers the we[] build

    // ---- compute: warp w handles row q0+w, all 4 views ----
    const int wid  = tid >> 5;
    const int lane = tid & 31;
    const int base = wid * ROW;

    // Congruence-slot accumulators. Slot j holds channel (j + lane%3) % 3.
    float m1[4][3], q2[4][3], pg[4][3];
    float m2[3], g2[3];
    #pragma unroll
    for (int v = 0; v < 4; v++)
        #pragma unroll
        for (int j = 0; j < 3; j++) { m1[v][j] = 0.f; q2[v][j] = 0.f; pg[v][j] = 0.f; }
    #pragma unroll
    for (int j = 0; j < 3; j++) { m2[j] = 0.f; g2[j] = 0.f; }

    // k = 0..10 full (352 elems), tail k=11 (11 lanes).
    #pragma unroll
    for (int k = 0; k < 11; k++) {
        const int e = k * 32 + lane;
        const int j = (2 * k) % 3;          // compile-time slot
        const float w = we[e];
        const float b = sG[base + e];
        const float wb = w * b;
        m2[j] += wb;
        g2[j] += wb * b;
        { float a = sP[0][base + e]; float wa = w * a;
          m1[0][j] += wa; q2[0][j] += wa * a; pg[0][j] += wa * b; }
        { float a = sP[1][base + e]; float wa = w * a;
          m1[1][j] += wa; q2[1][j] += wa * a; pg[1][j] += wa * b; }
        { float a = sP[2][base + e]; float wa = w * a;
          m1[2][j] += wa; q2[2][j] += wa * a; pg[2][j] += wa * b; }
        { float a = sP[3][base + e]; float wa = w * a;
          m1[3][j] += wa; q2[3][j] += wa * a; pg[3][j] += wa * b; }
    }
    if (lane < 11) {
        const int e = 352 + lane;
        const int j = 1;                    // (2*11)%3
        const float w = we[e];
        const float b = sG[base + e];
        const float wb = w * b;
        m2[j] += wb;
        g2[j] += wb * b;
        { float a = sP[0][base + e]; float wa = w * a;
          m1[0][j] += wa; q2[0][j] += wa * a; pg[0][j] += wa * b; }
        { float a = sP[1][base + e]; float wa = w * a;
          m1[1][j] += wa; q2[1][j] += wa * a; pg[1][j] += wa * b; }
        { float a = sP[2][base + e]; float wa = w * a;
          m1[2][j] += wa; q2[2][j] += wa * a; pg[2][j] += wa * b; }
        { float a = sP[3][base + e]; float wa = w * a;
          m1[3][j] += wa; q2[3][j] += wa * a; pg[3][j] += wa * b; }
    }

    // Rotate congruence slots into true channel order.
    //   r=0: (s0,s1,s2)  r=1: (s2,s0,s1)  r=2: (s1,s2,s0)
    const int r = lane - (lane / 3) * 3;
    const bool r1f = (r == 1);
    const bool r2f = (r == 2);
    #define ROT3(s) do { \
        float t0 = (s)[0], t1 = (s)[1], t2 = (s)[2]; \
        (s)[0] = r1f ? t2 : (r2f ? t1 : t0); \
        (s)[1] = r1f ? t0 : (r2f ? t2 : t1); \
        (s)[2] = r1f ? t1 : (r2f ? t0 : t2); \
    } while (0)
    #pragma unroll
    for (int v = 0; v < 4; v++) { ROT3(m1[v]); ROT3(q2[v]); ROT3(pg[v]); }
    ROT3(m2); ROT3(g2);
    #undef ROT3

    // Fold across lane-bit-16:
    //  lanes 0-15  -> views 0,1 + full-gt stats
    //  lanes 16-31 -> views 2,3 + full-gt stats
    const bool hi = (lane & 16) != 0;
    float val[24];
    #pragma unroll
    for (int j = 0; j < 3; j++) {
        float kA, kB;
        #define FOLD(slotA, slotB, idx) \
            kA = (slotA); kB = (slotB); \
            { float keep = hi ? kB : kA; float send = hi ? kA : kB; \
              val[idx] = keep + __shfl_xor_sync(0xFFFFFFFFu, send, 16); }
        FOLD(m1[0][j], m1[2][j], 0 + j);
        FOLD(q2[0][j], q2[2][j], 3 + j);
        FOLD(pg[0][j], pg[2][j], 6 + j);
        FOLD(m1[1][j], m1[3][j], 9 + j);
        FOLD(q2[1][j], q2[3][j], 12 + j);
        FOLD(pg[1][j], pg[3][j], 15 + j);
        FOLD(m2[j],    m2[j],    18 + j);   // single copy -> both halves get total
        FOLD(g2[j],    g2[j],    21 + j);
        #undef FOLD
    }

    // Butterfly within each 16-lane half.
    #pragma unroll
    for (int off = 8; off; off >>= 1) {
        #pragma unroll
        for (int i = 0; i < 24; i++)
            val[i] += __shfl_xor_sync(0xFFFFFFFFu, val[i], off);
    }

    // Epilogue.
    const float C1 = 1e-4f;   // 0.01^2
    const float C2 = 9e-4f;   // 0.03^2
    float ssim_lo = 0.f, ssim_hi_v = 0.f;
    #pragma unroll
    for (int c = 0; c < 3; c++) {
        float mu2  = val[18 + c];
        float mu2sq = mu2 * mu2;
        float s2   = val[21 + c] - mu2sq;
        {   // view lo
            float mu1 = val[0 + c];
            float mu1sq = mu1 * mu1;
            float mu12  = mu1 * mu2;
            float s1  = val[3 + c] - mu1sq;
            float s12 = val[6 + c] - mu12;
            float num = (2.0f * mu12 + C1) * (2.0f * s12 + C2);
            float den = (mu1sq + mu2sq + C1) * (s1 + s2 + C2);
            ssim_lo += __fdividef(num, den);
        }
        {   // view hi
            float mu1 = val[9 + c];
            float mu1sq = mu1 * mu1;
            float mu12  = mu1 * mu2;
            float s1  = val[12 + c] - mu1sq;
            float s12 = val[15 + c] - mu12;
            float num = (2.0f * mu12 + C1) * (2.0f * s12 + C2);
            float den = (mu1sq + mu2sq + C1) * (s1 + s2 + C2);
            ssim_hi_v += __fdividef(num, den);
        }
    }

    // Writers: lanes 0,1 (views 0,1) and 16,17 (views 2,3).
    if ((lane & 14) == 0) {
        const int q = q0 + wid;
        const int n = q >> 4;
        const int p = q & 15;
        int sel  = lane & 1;
        int view = ((lane >> 4) << 1) | sel;
        float res = (sel ? ssim_hi_v : ssim_lo) * (1.0f / 3.0f);
        out[(view * NN + n) * NP + p] = res;
    }
}

extern "C" void kernel_launch(void* const* d_in, const int* in_sizes, int n_in,
                              void* d_out, int out_size)
{
    const float* pred = (const float*)d_in[0];   // img_pred [4,2048,16,121,3]
    const float* gt   = (const float*)d_in[1];   // img_gt   [2048,16,121,3]
    float* out = (float*)d_out;                  // [4,2048,16]

    const int blocks = (NN * NP) / RPB;          // 8192 blocks, 4 rows each
    ssim_kernel<<<blocks, 128>>>(pred, gt, out);
}

// round 7
// speedup vs baseline: 2.1124x; 1.0815x over previous
#include <cuda_runtime.h>
#include <cstdint>

// SSIM over 11x11 patches — cp.async staging + patch-major smem compute.
// img_pred: [4, 2048, 16, 121, 3] f32   (~190 MB)
// img_gt:   [2048, 16, 121, 3] f32      (~47.6 MB)
// out:      [4, 2048, 16] f32
//
// R6 -> R7: compute now reads smem, where the 12B-stride patch-major gather
// is bank-conflict-free ((3*lane+c) mod 32 distinct). So drop the whole
// element-congruence + ROT3 apparatus (needed only for global coalescing):
// lane l handles patches l+32k, channel index is compile-time. Weights:
// one per patch (4 regs preloaded), zero-padded to 128 patches so the tail
// needs no predicates. Gaussian window built from a 6-entry 1-D table
// (6 expf per block) instead of ~11 expf per thread.

#define NN       2048
#define NP       16
#define ROW      363                       // 121 patches * 3 channels
#define VSTRIDE  ((size_t)NN * NP * ROW)   // floats per view
#define RPB      4                         // rows per block
#define CHUNK    (RPB * ROW)               // 1452 floats
#define CHUNK4   (CHUNK / 4)               // 363 float4
#define PADF     32                        // zeroed pad floats per array

__device__ __forceinline__ void cp16(uint32_t dst, const void* src) {
    asm volatile("cp.async.cg.shared.global [%0], [%1], 16;" :: "r"(dst), "l"(src));
}

__global__ __launch_bounds__(128) void ssim_kernel(
    const float* __restrict__ pred,
    const float* __restrict__ gt,
    float* __restrict__ out)
{
    __shared__ float sG[CHUNK + PADF];       // gt, 4 rows (+pad)
    __shared__ float sP[4][CHUNK + PADF];    // pred, 4 views x 4 rows (+pad)
    __shared__ float sg6[6];                 // 1-D gaussian, |d| = 0..5
    __shared__ float sW[128];                // per-patch weights, 0 for p>=121

    const int tid = threadIdx.x;
    const int q0  = blockIdx.x * RPB;        // first (n,p) row of this block

    // ---- stage: 5 streams x 363 float4 via cp.async (issue first) ----
    {
        const uint32_t dG = (uint32_t)__cvta_generic_to_shared(sG);
        const float4* __restrict__ srcG = (const float4*)(gt + (size_t)q0 * ROW);
        for (int i = tid; i < CHUNK4; i += 128)
            cp16(dG + i * 16, srcG + i);

        #pragma unroll
        for (int v = 0; v < 4; v++) {
            const uint32_t dP = (uint32_t)__cvta_generic_to_shared(sP[v]);
            const float4* __restrict__ srcP =
                (const float4*)(pred + v * VSTRIDE + (size_t)q0 * ROW);
            for (int i = tid; i < CHUNK4; i += 128)
                cp16(dP + i * 16, srcP + i);
        }
    }
    asm volatile("cp.async.commit_group;");

    // ---- while TMA-ish loads fly: zero pads, build weight table ----
    if (tid < PADF) {
        sG[CHUNK + tid] = 0.f;
        sP[0][CHUNK + tid] = 0.f;
        sP[1][CHUNK + tid] = 0.f;
        sP[2][CHUNK + tid] = 0.f;
        sP[3][CHUNK + tid] = 0.f;
    }
    if (tid < 6) {
        float d = (float)tid;
        sg6[tid] = expf(-d * d * (1.0f / 4.5f));   // sigma = 1.5
    }
    __syncthreads();
    {
        float S = sg6[0] + 2.0f * (sg6[1] + sg6[2] + sg6[3] + sg6[4] + sg6[5]);
        float invS2 = 1.0f / (S * S);
        if (tid < 121) {
            int py = tid / 11, px = tid % 11;
            int dy = py - 5; if (dy < 0) dy = -dy;
            int dx = px - 5; if (dx < 0) dx = -dx;
            sW[tid] = sg6[dy] * sg6[dx] * invS2;
        } else if (tid < 128) {
            sW[tid] = 0.f;                          // tail patches contribute 0
        }
    }
    asm volatile("cp.async.wait_group 0;");
    __syncthreads();

    // ---- compute: warp w handles row q0+w, all 4 views ----
    const int wid  = tid >> 5;
    const int lane = tid & 31;
    const int wbase = wid * ROW;

    float wk[4];
    #pragma unroll
    for (int k = 0; k < 4; k++) wk[k] = sW[k * 32 + lane];

    // Channel-indexed accumulators (no congruence/rotate needed).
    float m1[4][3], q2[4][3], pg[4][3];
    float m2[3], g2[3];
    #pragma unroll
    for (int v = 0; v < 4; v++)
        #pragma unroll
        for (int c = 0; c < 3; c++) { m1[v][c] = 0.f; q2[v][c] = 0.f; pg[v][c] = 0.f; }
    #pragma unroll
    for (int c = 0; c < 3; c++) { m2[c] = 0.f; g2[c] = 0.f; }

    #pragma unroll
    for (int k = 0; k < 4; k++) {
        const int base = wbase + 3 * (k * 32 + lane);
        const float w = wk[k];          // 0 for pad patches -> zero contribution
        const float b0 = sG[base + 0];
        const float b1 = sG[base + 1];
        const float b2 = sG[base + 2];
        const float wb0 = w * b0, wb1 = w * b1, wb2 = w * b2;
        m2[0] += wb0;       m2[1] += wb1;       m2[2] += wb2;
        g2[0] += wb0 * b0;  g2[1] += wb1 * b1;  g2[2] += wb2 * b2;

        #pragma unroll
        for (int v = 0; v < 4; v++) {
            const float a0 = sP[v][base + 0];
            const float a1 = sP[v][base + 1];
            const float a2 = sP[v][base + 2];
            const float wa0 = w * a0, wa1 = w * a1, wa2 = w * a2;
            m1[v][0] += wa0;       m1[v][1] += wa1;       m1[v][2] += wa2;
            q2[v][0] += wa0 * a0;  q2[v][1] += wa1 * a1;  q2[v][2] += wa2 * a2;
            pg[v][0] += wa0 * b0;  pg[v][1] += wa1 * b1;  pg[v][2] += wa2 * b2;
        }
    }

    // Fold across lane-bit-16:
    //  lanes 0-15  -> views 0,1 + full-gt stats
    //  lanes 16-31 -> views 2,3 + full-gt stats
    const bool hi = (lane & 16) != 0;
    float val[24];
    #pragma unroll
    for (int c = 0; c < 3; c++) {
        float kA, kB;
        #define FOLD(slotA, slotB, idx) \
            kA = (slotA); kB = (slotB); \
            { float keep = hi ? kB : kA; float send = hi ? kA : kB; \
              val[idx] = keep + __shfl_xor_sync(0xFFFFFFFFu, send, 16); }
        FOLD(m1[0][c], m1[2][c], 0 + c);
        FOLD(q2[0][c], q2[2][c], 3 + c);
        FOLD(pg[0][c], pg[2][c], 6 + c);
        FOLD(m1[1][c], m1[3][c], 9 + c);
        FOLD(q2[1][c], q2[3][c], 12 + c);
        FOLD(pg[1][c], pg[3][c], 15 + c);
        FOLD(m2[c],    m2[c],    18 + c);   // single copy -> both halves get total
        FOLD(g2[c],    g2[c],    21 + c);
        #undef FOLD
    }

    // Butterfly within each 16-lane half.
    #pragma unroll
    for (int off = 8; off; off >>= 1) {
        #pragma unroll
        for (int i = 0; i < 24; i++)
            val[i] += __shfl_xor_sync(0xFFFFFFFFu, val[i], off);
    }

    // Epilogue: each lane computes SSIM for its half's two views.
    const float C1 = 1e-4f;   // 0.01^2
    const float C2 = 9e-4f;   // 0.03^2
    float ssim_lo = 0.f, ssim_hi_v = 0.f;
    #pragma unroll
    for (int c = 0; c < 3; c++) {
        float mu2  = val[18 + c];
        float mu2sq = mu2 * mu2;
        float s2   = val[21 + c] - mu2sq;
        {   // view lo
            float mu1 = val[0 + c];
            float mu1sq = mu1 * mu1;
            float mu12  = mu1 * mu2;
            float s1  = val[3 + c] - mu1sq;
            float s12 = val[6 + c] - mu12;
            float num = (2.0f * mu12 + C1) * (2.0f * s12 + C2);
            float den = (mu1sq + mu2sq + C1) * (s1 + s2 + C2);
            ssim_lo += __fdividef(num, den);
        }
        {   // view hi
            float mu1 = val[9 + c];
            float mu1sq = mu1 * mu1;
            float mu12  = mu1 * mu2;
            float s1  = val[12 + c] - mu1sq;
            float s12 = val[15 + c] - mu12;
            float num = (2.0f * mu12 + C1) * (2.0f * s12 + C2);
            float den = (mu1sq + mu2sq + C1) * (s1 + s2 + C2);
            ssim_hi_v += __fdividef(num, den);
        }
    }

    // Writers: lanes 0,1 (views 0,1) and 16,17 (views 2,3).
    if ((lane & 14) == 0) {
        const int q = q0 + wid;
        const int n = q >> 4;
        const int p = q & 15;
        int sel  = lane & 1;
        int view = ((lane >> 4) << 1) | sel;
        float res = (sel ? ssim_hi_v : ssim_lo) * (1.0f / 3.0f);
        out[(view * NN + n) * NP + p] = res;
    }
}

extern "C" void kernel_launch(void* const* d_in, const int* in_sizes, int n_in,
                              void* d_out, int out_size)
{
    const float* pred = (const float*)d_in[0];   // img_pred [4,2048,16,121,3]
    const float* gt   = (const float*)d_in[1];   // img_gt   [2048,16,121,3]
    float* out = (float*)d_out;                  // [4,2048,16]

    const int blocks = (NN * NP) / RPB;          // 8192 blocks, 4 rows each
    ssim_kernel<<<blocks, 128>>>(pred, gt, out);
}